// round 13
// baseline (speedup 1.0000x reference)
#include <cuda_runtime.h>

__device__ __forceinline__ float dot4acc(float acc, float4 a, float4 b) {
    acc = fmaf(a.x, b.x, acc);
    acc = fmaf(a.y, b.y, acc);
    acc = fmaf(a.z, b.z, acc);
    acc = fmaf(a.w, b.w, acc);
    return acc;
}

// Paired reduction: returns full-warp sum of a in even lanes, of b in odd lanes.
__device__ __forceinline__ float pair_reduce(float a, float b, int lane) {
    float send = (lane & 1) ? a : b;
    float keep = (lane & 1) ? b : a;
    float u = keep + __shfl_xor_sync(0xffffffffu, send, 1);
    u += __shfl_xor_sync(0xffffffffu, u, 2);
    u += __shfl_xor_sync(0xffffffffu, u, 4);
    u += __shfl_xor_sync(0xffffffffu, u, 8);
    u += __shfl_xor_sync(0xffffffffu, u, 16);
    return u;
}

// Issue one sample's 4 cp.async (this lane's own k-slice only). 2KB slot stride.
__device__ __forceinline__ void issue_sample(const float4* gbase, int s_local,
                                             unsigned ring_lane, int slot) {
    const float4* g = gbase + (size_t)s_local * 128;
    unsigned sa = ring_lane + (unsigned)slot * 2048u;
    asm volatile("cp.async.cg.shared.global [%0], [%1], 16;" :: "r"(sa),         "l"(g) : "memory");
    asm volatile("cp.async.cg.shared.global [%0], [%1], 16;" :: "r"(sa + 512u),  "l"(g + 32) : "memory");
    asm volatile("cp.async.cg.shared.global [%0], [%1], 16;" :: "r"(sa + 1024u), "l"(g + 64) : "memory");
    asm volatile("cp.async.cg.shared.global [%0], [%1], 16;" :: "r"(sa + 1536u), "l"(g + 96) : "memory");
}
#define CP_COMMIT() asm volatile("cp.async.commit_group;" ::: "memory")
#define CP_WAIT3()  asm volatile("cp.async.wait_group 3;" ::: "memory")
#define CP_WAIT0()  asm volatile("cp.async.wait_group 0;" ::: "memory")

#define NSLOT 5

__global__ void __launch_bounds__(128, 4)
qnet_kernel(const float4* __restrict__ X,   // [B, 128] float4 view of [B,512]
            const float4* __restrict__ W4,  // [4, 128] float4 view of pre_W [4,512]
            const float* __restrict__ preb, // [4]
            const float* __restrict__ qp,   // [60]
            const float* __restrict__ postW,// [8]
            const float* __restrict__ postb,// [2]
            float2* __restrict__ out,       // [B] float2 view of [B,2]
            int nChunks)                    // B/32
{
    __shared__ float sh[64];                    // [0:48) cs, [48:56) postW, [56:58) postb, [58:62) preb
    __shared__ float4 ring[4][NSLOT][128];      // [warp][slot][pos]  (40KB)

    int t = threadIdx.x;
    if (t < 24) {
        float s, c;
        sincosf(qp[4 + t] * 0.5f, &s, &c);
        sh[2 * t]     = c;
        sh[2 * t + 1] = s;
    } else if (t < 32) {
        sh[48 + (t - 24)] = postW[t - 24];
    } else if (t < 34) {
        sh[56 + (t - 32)] = postb[t - 32];
    } else if (t < 38) {
        sh[58 + (t - 34)] = preb[t - 34];
    }
    __syncthreads();

    const int lane = t & 31;
    const int warp = t >> 5;
    const int gwarp = blockIdx.x * 4 + warp;
    const int totalWarps = gridDim.x * 4;

    const unsigned ring_lane =
        (unsigned)__cvta_generic_to_shared(&ring[warp][0][0]) + (unsigned)lane * 16u;

    // Per-lane register slice of pre_W: 4 outputs x 4 float4
    float4 wv[4][4];
#pragma unroll
    for (int o = 0; o < 4; o++)
#pragma unroll
        for (int i = 0; i < 4; i++)
            wv[o][i] = W4[o * 128 + 32 * i + lane];

    const float pb0 = sh[58], pb1 = sh[59], pb2 = sh[60], pb3 = sh[61];
    const float4* ringv = &ring[warp][0][0];

    // slA = ring slot holding the current chunk's sample sb. Advances +2 mod 5
    // per pair-iteration; 32 samples/chunk => +32 ≡ +2 mod 5 across chunks,
    // carried naturally by keeping slA live across the chunk loop.
    int slA = 0;
    bool primed = false;

    for (int chunk = gwarp; chunk < nChunks; chunk += totalWarps) {
        const size_t m0 = (size_t)chunk << 5;
        const float4* xb = X + m0 * 128 + lane;
        const int chunkN = chunk + totalWarps;
        const float4* xbN = (chunkN < nChunks)
                              ? X + ((size_t)chunkN << 5) * 128 + lane
                              : (const float4*)0;

        if (!primed) {   // first chunk of this warp: prime 4 samples deep
            issue_sample(xb, 0, ring_lane, 0); CP_COMMIT();
            issue_sample(xb, 1, ring_lane, 1); CP_COMMIT();
            issue_sample(xb, 2, ring_lane, 2); CP_COMMIT();
            issue_sample(xb, 3, ring_lane, 3); CP_COMMIT();
            primed = true;
        }

        float r0 = 0.f, r1 = 0.f, r2 = 0.f, r3 = 0.f;  // this lane's sample result

#pragma unroll 2
        for (int sb = 0; sb < 32; sb += 2) {
            // incremental slot registers (replace all % NSLOT)
            int slB = slA + 1; if (slB >= NSLOT) slB -= NSLOT;
            int slI = slA + 4; if (slI >= NSLOT) slI -= NSLOT;

            // prefetch sample sb+4 into slot slI (freed last iteration)
            {
                int si = sb + 4;
                if (si < 32)  issue_sample(xb,  si,      ring_lane, slI);
                else if (xbN) issue_sample(xbN, si - 32, ring_lane, slI);
                CP_COMMIT();
            }
            CP_WAIT3();   // all but newest 3 groups complete => sb, sb+1 ready

            float a0, a1, a2, a3;
            {
                const float4* sp = ringv + (size_t)slA * 128 + lane;
                float4 x0 = sp[0], x1 = sp[32], x2 = sp[64], x3 = sp[96];
                a0 = dot4acc(dot4acc(dot4acc(dot4acc(0.f, x0, wv[0][0]), x1, wv[0][1]), x2, wv[0][2]), x3, wv[0][3]);
                a1 = dot4acc(dot4acc(dot4acc(dot4acc(0.f, x0, wv[1][0]), x1, wv[1][1]), x2, wv[1][2]), x3, wv[1][3]);
                a2 = dot4acc(dot4acc(dot4acc(dot4acc(0.f, x0, wv[2][0]), x1, wv[2][1]), x2, wv[2][2]), x3, wv[2][3]);
                a3 = dot4acc(dot4acc(dot4acc(dot4acc(0.f, x0, wv[3][0]), x1, wv[3][1]), x2, wv[3][2]), x3, wv[3][3]);
            }

            // prefetch sample sb+5 into slot slA (just consumed; +5 ≡ 0 mod 5)
            {
                int si = sb + 5;
                if (si < 32)  issue_sample(xb,  si,      ring_lane, slA);
                else if (xbN) issue_sample(xbN, si - 32, ring_lane, slA);
                CP_COMMIT();
            }

            float b0, b1, b2, b3;
            {
                const float4* sp = ringv + (size_t)slB * 128 + lane;
                float4 x0 = sp[0], x1 = sp[32], x2 = sp[64], x3 = sp[96];
                b0 = dot4acc(dot4acc(dot4acc(dot4acc(0.f, x0, wv[0][0]), x1, wv[0][1]), x2, wv[0][2]), x3, wv[0][3]);
                b1 = dot4acc(dot4acc(dot4acc(dot4acc(0.f, x0, wv[1][0]), x1, wv[1][1]), x2, wv[1][2]), x3, wv[1][3]);
                b2 = dot4acc(dot4acc(dot4acc(dot4acc(0.f, x0, wv[2][0]), x1, wv[2][1]), x2, wv[2][2]), x3, wv[2][3]);
                b3 = dot4acc(dot4acc(dot4acc(dot4acc(0.f, x0, wv[3][0]), x1, wv[3][1]), x2, wv[3][2]), x3, wv[3][3]);
            }

            // Paired reductions (20 SHFLs): even lanes get sum(a*), odd get sum(b*).
            float u0 = pair_reduce(a0, b0, lane);
            float u1 = pair_reduce(a1, b1, lane);
            float u2 = pair_reduce(a2, b2, lane);
            float u3 = pair_reduce(a3, b3, lane);

            if (lane == sb)     { r0 = u0; r1 = u1; r2 = u2; r3 = u3; }  // even
            if (lane == sb + 1) { r0 = u0; r1 = u1; r2 = u2; r3 = u3; }  // odd

            // advance slot: +2 mod NSLOT
            slA += 2; if (slA >= NSLOT) slA -= NSLOT;
        }

        // ---- per-lane quantum circuit for sample m0 + lane ----
        float cw[4], sw[4];
        {
            float pre[4] = {r0 + pb0, r1 + pb1, r2 + pb2, r3 + pb3};
#pragma unroll
            for (int w = 0; w < 4; w++) {
                float e  = __expf(2.0f * pre[w]);
                float th = 1.0f - 2.0f / (e + 1.0f);        // tanh(pre)
                __sincosf(th * 0.78539816339744830961f, &sw[w], &cw[w]);
            }
        }

        float st[16];
        {
            float A0 = cw[0] - sw[0], B0 = cw[0] + sw[0];
            float A1 = cw[1] - sw[1], B1 = cw[1] + sw[1];
            float A2 = cw[2] - sw[2], B2 = cw[2] + sw[2];
            float A3 = cw[3] - sw[3], B3 = cw[3] + sw[3];
            float g4[4] = {0.25f * A0 * A1, 0.25f * A0 * B1,
                           0.25f * B0 * A1, 0.25f * B0 * B1};
            float h4[4] = {A2 * A3, A2 * B3, B2 * A3, B2 * B3};
#pragma unroll
            for (int a = 0; a < 4; a++)
#pragma unroll
                for (int b = 0; b < 4; b++)
                    st[4 * a + b] = g4[a] * h4[b];
        }

#pragma unroll
        for (int k = 0; k < 6; k++) {
#pragma unroll
            for (int j = 0; j < 4; j++) {
                float tmp = st[8 + j]; st[8 + j] = st[12 + j]; st[12 + j] = tmp;
            }
#pragma unroll
            for (int j = 0; j < 4; j++) {
                int i = 4 * j + 2;
                float tmp = st[i]; st[i] = st[i + 1]; st[i + 1] = tmp;
            }
            {
                float tmp;
                tmp = st[4];  st[4]  = st[6];  st[6]  = tmp;
                tmp = st[5];  st[5]  = st[7];  st[7]  = tmp;
                tmp = st[12]; st[12] = st[14]; st[14] = tmp;
                tmp = st[13]; st[13] = st[15]; st[15] = tmp;
            }
#pragma unroll
            for (int w = 0; w < 4; w++) {
                float cc = sh[2 * (4 * k + w)];
                float ss = sh[2 * (4 * k + w) + 1];
                const int bit = 8 >> w;
#pragma unroll
                for (int i = 0; i < 16; i++) {
                    if ((i & bit) == 0) {
                        float s0 = st[i], s1 = st[i | bit];
                        st[i]       = fmaf(cc, s0, -ss * s1);
                        st[i | bit] = fmaf(ss, s0,  cc * s1);
                    }
                }
            }
        }

        float z0 = 0.f, z1 = 0.f, z2 = 0.f, z3 = 0.f;
#pragma unroll
        for (int i = 0; i < 16; i++) {
            float sp = st[i];
            z0 = fmaf((i & 8) ? -sp : sp, sp, z0);
            z1 = fmaf((i & 4) ? -sp : sp, sp, z1);
            z2 = fmaf((i & 2) ? -sp : sp, sp, z2);
            z3 = fmaf((i & 1) ? -sp : sp, sp, z3);
        }

        float o0 = sh[56], o1 = sh[57];
        o0 = fmaf(sh[48 + 0], z0, o0);
        o0 = fmaf(sh[48 + 1], z1, o0);
        o0 = fmaf(sh[48 + 2], z2, o0);
        o0 = fmaf(sh[48 + 3], z3, o0);
        o1 = fmaf(sh[48 + 4], z0, o1);
        o1 = fmaf(sh[48 + 5], z1, o1);
        o1 = fmaf(sh[48 + 6], z2, o1);
        o1 = fmaf(sh[48 + 7], z3, o1);

        // Streaming store: write-once output, keep it out of L2's hot sets.
        __stcs(&out[m0 + lane], make_float2(o0, o1));
    }
    CP_WAIT0();
}

extern "C" void kernel_launch(void* const* d_in, const int* in_sizes, int n_in,
                              void* d_out, int out_size) {
    const float* X     = (const float*)d_in[0];  // [B,512]
    const float* preW  = (const float*)d_in[1];  // [4,512]
    const float* preb  = (const float*)d_in[2];  // [4]
    const float* qp    = (const float*)d_in[3];  // [60]
    const float* postW = (const float*)d_in[4];  // [2,4]
    const float* postb = (const float*)d_in[5];  // [2]

    int B = in_sizes[0] / 512;
    int nChunks = B >> 5;

    // R4/R8/R10-proven geometry: 592 blocks (4 resident blocks/SM on 148 SMs),
    // 4 warps each, grid-stride over chunks.
    int grid = 592;
    int maxUseful = (nChunks + 3) / 4;   // never launch more warps than chunks
    if (grid > maxUseful) grid = maxUseful;
    if (grid < 1) grid = 1;

    qnet_kernel<<<grid, 128>>>((const float4*)X, (const float4*)preW,
                               preb, qp, postW, postb,
                               (float2*)d_out, nChunks);
}

// round 14
// speedup vs baseline: 1.0136x; 1.0136x over previous
#include <cuda_runtime.h>

__device__ __forceinline__ float dot4acc(float acc, float4 a, float4 b) {
    acc = fmaf(a.x, b.x, acc);
    acc = fmaf(a.y, b.y, acc);
    acc = fmaf(a.z, b.z, acc);
    acc = fmaf(a.w, b.w, acc);
    return acc;
}

// Paired reduction: returns full-warp sum of a in even lanes, of b in odd lanes.
__device__ __forceinline__ float pair_reduce(float a, float b, int lane) {
    float send = (lane & 1) ? a : b;
    float keep = (lane & 1) ? b : a;
    float u = keep + __shfl_xor_sync(0xffffffffu, send, 1);
    u += __shfl_xor_sync(0xffffffffu, u, 2);
    u += __shfl_xor_sync(0xffffffffu, u, 4);
    u += __shfl_xor_sync(0xffffffffu, u, 8);
    u += __shfl_xor_sync(0xffffffffu, u, 16);
    return u;
}

// Issue one sample's 4 cp.async (this lane's own k-slice only). 2KB slot stride.
__device__ __forceinline__ void issue_sample(const float4* gbase, int s_local,
                                             unsigned ring_lane, int slot) {
    const float4* g = gbase + (size_t)s_local * 128;
    unsigned sa = ring_lane + (unsigned)slot * 2048u;
    asm volatile("cp.async.cg.shared.global [%0], [%1], 16;" :: "r"(sa),         "l"(g) : "memory");
    asm volatile("cp.async.cg.shared.global [%0], [%1], 16;" :: "r"(sa + 512u),  "l"(g + 32) : "memory");
    asm volatile("cp.async.cg.shared.global [%0], [%1], 16;" :: "r"(sa + 1024u), "l"(g + 64) : "memory");
    asm volatile("cp.async.cg.shared.global [%0], [%1], 16;" :: "r"(sa + 1536u), "l"(g + 96) : "memory");
}
#define CP_COMMIT() asm volatile("cp.async.commit_group;" ::: "memory")
#define CP_WAIT3()  asm volatile("cp.async.wait_group 3;" ::: "memory")
#define CP_WAIT0()  asm volatile("cp.async.wait_group 0;" ::: "memory")

#define NSLOT 5

__global__ void __launch_bounds__(128, 4)
qnet_kernel(const float4* __restrict__ X,   // [B, 128] float4 view of [B,512]
            const float4* __restrict__ W4,  // [4, 128] float4 view of pre_W [4,512]
            const float* __restrict__ preb, // [4]
            const float* __restrict__ qp,   // [60]
            const float* __restrict__ postW,// [8]
            const float* __restrict__ postb,// [2]
            float2* __restrict__ out,       // [B] float2 view of [B,2]
            int nChunks)                    // B/32
{
    __shared__ float sh[64];                    // [0:48) cs, [48:56) postW, [56:58) postb, [58:62) preb
    __shared__ float4 ring[4][NSLOT][128];      // [warp][slot][pos]  (40KB)

    int t = threadIdx.x;
    if (t < 24) {
        float s, c;
        sincosf(qp[4 + t] * 0.5f, &s, &c);
        sh[2 * t]     = c;
        sh[2 * t + 1] = s;
    } else if (t < 32) {
        sh[48 + (t - 24)] = postW[t - 24];
    } else if (t < 34) {
        sh[56 + (t - 32)] = postb[t - 32];
    } else if (t < 38) {
        sh[58 + (t - 34)] = preb[t - 34];
    }
    __syncthreads();

    const int lane = t & 31;
    const int warp = t >> 5;
    const int gwarp = blockIdx.x * 4 + warp;
    const int totalWarps = gridDim.x * 4;

    const unsigned ring_lane =
        (unsigned)__cvta_generic_to_shared(&ring[warp][0][0]) + (unsigned)lane * 16u;

    // Per-lane register slice of pre_W: 4 outputs x 4 float4
    float4 wv[4][4];
#pragma unroll
    for (int o = 0; o < 4; o++)
#pragma unroll
        for (int i = 0; i < 4; i++)
            wv[o][i] = W4[o * 128 + 32 * i + lane];

    const float pb0 = sh[58], pb1 = sh[59], pb2 = sh[60], pb3 = sh[61];
    const float4* ringv = &ring[warp][0][0];

    int slot_base = 0;  // slot of current chunk's sample 0
    bool primed = false;

    for (int chunk = gwarp; chunk < nChunks; chunk += totalWarps) {
        const size_t m0 = (size_t)chunk << 5;
        const float4* xb = X + m0 * 128 + lane;
        const int chunkN = chunk + totalWarps;
        const float4* xbN = (chunkN < nChunks)
                              ? X + ((size_t)chunkN << 5) * 128 + lane
                              : (const float4*)0;

        if (!primed) {   // first chunk of this warp: prime 4 samples deep
            issue_sample(xb, 0, ring_lane, 0); CP_COMMIT();
            issue_sample(xb, 1, ring_lane, 1); CP_COMMIT();
            issue_sample(xb, 2, ring_lane, 2); CP_COMMIT();
            issue_sample(xb, 3, ring_lane, 3); CP_COMMIT();
            primed = true;
        }

        float r0 = 0.f, r1 = 0.f, r2 = 0.f, r3 = 0.f;  // this lane's sample result

#pragma unroll 2
        for (int sb = 0; sb < 32; sb += 2) {
            // prefetch sample sb+4 (slot freed last iteration)
            {
                int si = sb + 4;
                int sl = (slot_base + si) % NSLOT;
                if (si < 32)  issue_sample(xb,  si,      ring_lane, sl);
                else if (xbN) issue_sample(xbN, si - 32, ring_lane, sl);
                CP_COMMIT();
            }
            CP_WAIT3();   // all but newest 3 groups complete => sb, sb+1 ready

            const int slA = (slot_base + sb) % NSLOT;
            const int slB = (slot_base + sb + 1) % NSLOT;

            float a0, a1, a2, a3;
            {
                const float4* sp = ringv + (size_t)slA * 128 + lane;
                float4 x0 = sp[0], x1 = sp[32], x2 = sp[64], x3 = sp[96];
                a0 = dot4acc(dot4acc(dot4acc(dot4acc(0.f, x0, wv[0][0]), x1, wv[0][1]), x2, wv[0][2]), x3, wv[0][3]);
                a1 = dot4acc(dot4acc(dot4acc(dot4acc(0.f, x0, wv[1][0]), x1, wv[1][1]), x2, wv[1][2]), x3, wv[1][3]);
                a2 = dot4acc(dot4acc(dot4acc(dot4acc(0.f, x0, wv[2][0]), x1, wv[2][1]), x2, wv[2][2]), x3, wv[2][3]);
                a3 = dot4acc(dot4acc(dot4acc(dot4acc(0.f, x0, wv[3][0]), x1, wv[3][1]), x2, wv[3][2]), x3, wv[3][3]);
            }

            // prefetch sample sb+5 (slot slA just consumed)
            {
                int si = sb + 5;
                int sl = (slot_base + si) % NSLOT;
                if (si < 32)  issue_sample(xb,  si,      ring_lane, sl);
                else if (xbN) issue_sample(xbN, si - 32, ring_lane, sl);
                CP_COMMIT();
            }

            float b0, b1, b2, b3;
            {
                const float4* sp = ringv + (size_t)slB * 128 + lane;
                float4 x0 = sp[0], x1 = sp[32], x2 = sp[64], x3 = sp[96];
                b0 = dot4acc(dot4acc(dot4acc(dot4acc(0.f, x0, wv[0][0]), x1, wv[0][1]), x2, wv[0][2]), x3, wv[0][3]);
                b1 = dot4acc(dot4acc(dot4acc(dot4acc(0.f, x0, wv[1][0]), x1, wv[1][1]), x2, wv[1][2]), x3, wv[1][3]);
                b2 = dot4acc(dot4acc(dot4acc(dot4acc(0.f, x0, wv[2][0]), x1, wv[2][1]), x2, wv[2][2]), x3, wv[2][3]);
                b3 = dot4acc(dot4acc(dot4acc(dot4acc(0.f, x0, wv[3][0]), x1, wv[3][1]), x2, wv[3][2]), x3, wv[3][3]);
            }

            // Paired reductions (20 SHFLs): even lanes get sum(a*), odd get sum(b*).
            float u0 = pair_reduce(a0, b0, lane);
            float u1 = pair_reduce(a1, b1, lane);
            float u2 = pair_reduce(a2, b2, lane);
            float u3 = pair_reduce(a3, b3, lane);

            if (lane == sb)     { r0 = u0; r1 = u1; r2 = u2; r3 = u3; }  // even
            if (lane == sb + 1) { r0 = u0; r1 = u1; r2 = u2; r3 = u3; }  // odd
        }

        // advance slot base: 32 samples consumed, 32 % NSLOT = 2
        slot_base = (slot_base + 32) % NSLOT;

        // ---- per-lane quantum circuit for sample m0 + lane ----
        float cw[4], sw[4];
        {
            float pre[4] = {r0 + pb0, r1 + pb1, r2 + pb2, r3 + pb3};
#pragma unroll
            for (int w = 0; w < 4; w++) {
                float e  = __expf(2.0f * pre[w]);
                float th = 1.0f - 2.0f / (e + 1.0f);        // tanh(pre)
                __sincosf(th * 0.78539816339744830961f, &sw[w], &cw[w]);
            }
        }

        float st[16];
        {
            float A0 = cw[0] - sw[0], B0 = cw[0] + sw[0];
            float A1 = cw[1] - sw[1], B1 = cw[1] + sw[1];
            float A2 = cw[2] - sw[2], B2 = cw[2] + sw[2];
            float A3 = cw[3] - sw[3], B3 = cw[3] + sw[3];
            float g4[4] = {0.25f * A0 * A1, 0.25f * A0 * B1,
                           0.25f * B0 * A1, 0.25f * B0 * B1};
            float h4[4] = {A2 * A3, A2 * B3, B2 * A3, B2 * B3};
#pragma unroll
            for (int a = 0; a < 4; a++)
#pragma unroll
                for (int b = 0; b < 4; b++)
                    st[4 * a + b] = g4[a] * h4[b];
        }

#pragma unroll
        for (int k = 0; k < 6; k++) {
#pragma unroll
            for (int j = 0; j < 4; j++) {
                float tmp = st[8 + j]; st[8 + j] = st[12 + j]; st[12 + j] = tmp;
            }
#pragma unroll
            for (int j = 0; j < 4; j++) {
                int i = 4 * j + 2;
                float tmp = st[i]; st[i] = st[i + 1]; st[i + 1] = tmp;
            }
            {
                float tmp;
                tmp = st[4];  st[4]  = st[6];  st[6]  = tmp;
                tmp = st[5];  st[5]  = st[7];  st[7]  = tmp;
                tmp = st[12]; st[12] = st[14]; st[14] = tmp;
                tmp = st[13]; st[13] = st[15]; st[15] = tmp;
            }
#pragma unroll
            for (int w = 0; w < 4; w++) {
                float cc = sh[2 * (4 * k + w)];
                float ss = sh[2 * (4 * k + w) + 1];
                const int bit = 8 >> w;
#pragma unroll
                for (int i = 0; i < 16; i++) {
                    if ((i & bit) == 0) {
                        float s0 = st[i], s1 = st[i | bit];
                        st[i]       = fmaf(cc, s0, -ss * s1);
                        st[i | bit] = fmaf(ss, s0,  cc * s1);
                    }
                }
            }
        }

        float z0 = 0.f, z1 = 0.f, z2 = 0.f, z3 = 0.f;
#pragma unroll
        for (int i = 0; i < 16; i++) {
            float sp = st[i];
            z0 = fmaf((i & 8) ? -sp : sp, sp, z0);
            z1 = fmaf((i & 4) ? -sp : sp, sp, z1);
            z2 = fmaf((i & 2) ? -sp : sp, sp, z2);
            z3 = fmaf((i & 1) ? -sp : sp, sp, z3);
        }

        float o0 = sh[56], o1 = sh[57];
        o0 = fmaf(sh[48 + 0], z0, o0);
        o0 = fmaf(sh[48 + 1], z1, o0);
        o0 = fmaf(sh[48 + 2], z2, o0);
        o0 = fmaf(sh[48 + 3], z3, o0);
        o1 = fmaf(sh[48 + 4], z0, o1);
        o1 = fmaf(sh[48 + 5], z1, o1);
        o1 = fmaf(sh[48 + 6], z2, o1);
        o1 = fmaf(sh[48 + 7], z3, o1);

        // Streaming store: write-once output, keep it out of L2's hot sets.
        __stcs(&out[m0 + lane], make_float2(o0, o1));
    }
    CP_WAIT0();
}

extern "C" void kernel_launch(void* const* d_in, const int* in_sizes, int n_in,
                              void* d_out, int out_size) {
    const float* X     = (const float*)d_in[0];  // [B,512]
    const float* preW  = (const float*)d_in[1];  // [4,512]
    const float* preb  = (const float*)d_in[2];  // [4]
    const float* qp    = (const float*)d_in[3];  // [60]
    const float* postW = (const float*)d_in[4];  // [2,4]
    const float* postb = (const float*)d_in[5];  // [2]

    int B = in_sizes[0] / 512;
    int nChunks = B >> 5;

    // R4/R8/R10/R12-proven geometry: 592 blocks (4 resident blocks/SM on
    // 148 SMs), 4 warps each, grid-stride over chunks.
    int grid = 592;
    int maxUseful = (nChunks + 3) / 4;   // never launch more warps than chunks
    if (grid > maxUseful) grid = maxUseful;
    if (grid < 1) grid = 1;

    qnet_kernel<<<grid, 128>>>((const float4*)X, (const float4*)preW,
                               preb, qp, postW, postb,
                               (float2*)d_out, nChunks);
}